// round 7
// baseline (speedup 1.0000x reference)
#include <cuda_runtime.h>
#include <cstddef>
#include <cstdint>

// Problem constants (fixed by setup_inputs)
#define RB   12
#define LB   32
#define MB   16
#define HHB  32
#define HFB  64
#define EB   132
#define BTOT 64
#define NB_PER 8              // batches per block
#define NGROUP (BTOT/NB_PER)  // 8 groups
#define NBLOCKS (NGROUP*RB)   // 96 blocks = 8 clusters of 12
#define NTHREADS 256          // 8 warps

// padded strides (mod 32 in {4,20} -> conflict-free 8-batch wavefronts)
#define ZSTR  436   // per-batch stride in zsD   (436 % 32 == 20)
#define MSTR  180   // per-batch stride in meanT (180 % 32 == 20)
#define ISTR  36    // per-batch stride in incT/hgT (36 % 32 == 4)
#define HSTR  68    // per-batch stride in hbufT (68 % 32 == 4)

struct __align__(16) SmemLayout {
    unsigned long long mbar[2];
    // weights, row-per-output, padded strides
    float mw2[176*36];     // [(slot*16+m)][k]
    float awT[32*MSTR];    // [l][slot*16+m]
    float mb [176];
    float gsw2[32*36];
    float gcw2[32*36];
    float gsb[32];
    float lw2[64*68];      // [o][i 0..63]
    float lbS[64];
    float ow2[32*68];      // [l][hf]
    float obS[32];
    float wih2[96*36];
    float whh2[96*36];
    float bihS[96];
    float bhhS[96];
    // activations, batch-padded
    float zsD [2][NB_PER*ZSTR];   // [buf][b*ZSTR + r*36 + i]
    float meanT[NB_PER*MSTR];     // [b*MSTR + row]
    float incT [NB_PER*ISTR];     // [b*ISTR + l]
    float hbufT[NB_PER*HSTR];     // [b*HSTR + o]
    float hgT  [NB_PER*ISTR];     // [b*ISTR + j]
    int   elist[12];
    int   slist[12];
};

__device__ __forceinline__ float fsig(float x) { return 1.0f / (1.0f + __expf(-x)); }

__device__ __forceinline__ uint32_t smem_u32(const void* p) {
    uint32_t a;
    asm("{ .reg .u64 t; cvta.to.shared.u64 t, %1; cvt.u32.u64 %0, t; }"
        : "=r"(a) : "l"(p));
    return a;
}
__device__ __forceinline__ uint32_t mapa_rank(uint32_t laddr, uint32_t rank) {
    uint32_t r;
    asm("mapa.shared::cluster.u32 %0, %1, %2;" : "=r"(r) : "r"(laddr), "r"(rank));
    return r;
}
__device__ __forceinline__ void st_remote_f32(uint32_t addr, float v) {
    asm volatile("st.shared::cluster.f32 [%0], %1;" :: "r"(addr), "f"(v) : "memory");
}
__device__ __forceinline__ void mbar_arrive_remote(uint32_t addr) {
    asm volatile("mbarrier.arrive.release.cluster.shared::cluster.b64 _, [%0];"
                 :: "r"(addr) : "memory");
}
__device__ __forceinline__ void mbar_init(uint32_t addr, uint32_t cnt) {
    asm volatile("mbarrier.init.shared.b64 [%0], %1;" :: "r"(addr), "r"(cnt) : "memory");
}
__device__ __forceinline__ void mbar_wait(uint32_t addr, uint32_t parity) {
    uint32_t done;
    do {
        asm volatile(
            "{\n\t.reg .pred p;\n\t"
            "mbarrier.try_wait.parity.acquire.cluster.shared::cta.b64 p, [%1], %2, 0x989680;\n\t"
            "selp.b32 %0, 1, 0, p;\n\t}"
            : "=r"(done) : "r"(addr), "r"(parity) : "memory");
    } while (!done);
}
__device__ __forceinline__ void cluster_sync_all() {
    asm volatile("barrier.cluster.arrive.aligned;" ::: "memory");
    asm volatile("barrier.cluster.wait.aligned;" ::: "memory");
}

// dot-32 over float4: 2 accumulators
#define DOT32(acc0, acc1, WP, AP)                                    \
    {                                                                \
        _Pragma("unroll")                                            \
        for (int q = 0; q < 8; q++) {                                \
            float4 x = (WP)[q], a = (AP)[q];                         \
            acc0 = fmaf(x.x, a.x, acc0); acc1 = fmaf(x.y, a.y, acc1);\
            acc0 = fmaf(x.z, a.z, acc0); acc1 = fmaf(x.w, a.w, acc1);\
        }                                                            \
    }

__global__ void __launch_bounds__(NTHREADS, 1) __cluster_dims__(RB, 1, 1)
nv_main_kernel(
    const float* __restrict__ z0,  const float* __restrict__ h0,
    const float* __restrict__ mean_w, const float* __restrict__ mean_b,
    const float* __restrict__ add_w,
    const float* __restrict__ gsw, const float* __restrict__ gsb_g,
    const float* __restrict__ gcw,
    const float* __restrict__ lw,  const float* __restrict__ lb_g,
    const float* __restrict__ ow,  const float* __restrict__ ob_g,
    const float* __restrict__ wih, const float* __restrict__ whh,
    const float* __restrict__ bih_g, const float* __restrict__ bhh_g,
    const int* __restrict__ src_idx, const int* __restrict__ tgt_idx,
    int T,
    float* __restrict__ zt, float* __restrict__ hf, float* __restrict__ ms)
{
    extern __shared__ char smraw[];
    SmemLayout& sm = *reinterpret_cast<SmemLayout*>(smraw);
    const int tid = threadIdx.x;
    const int g = blockIdx.x / RB;
    const int r = blockIdx.x % RB;
    const int b0 = g * NB_PER;

    // ---- incoming-edge list ----
    for (int e = tid; e < EB; e += NTHREADS) {
        if (tgt_idx[e] == r) {
            int s = src_idx[e];
            int slot = (s < r) ? s : s - 1;
            sm.elist[slot] = e;
            sm.slist[slot] = s;
        }
    }
    if (tid < 2) mbar_init(smem_u32(&sm.mbar[tid]), 88);
    __syncthreads();

    // ---- cache weights ----
    for (int idx = tid; idx < 176*32; idx += NTHREADS) {
        int row = idx >> 5, k = idx & 31;
        int slot = row >> 4, m = row & 15;
        sm.mw2[row*36 + k] = mean_w[((size_t)sm.elist[slot]*MB + m)*LB + k];
    }
    for (int idx = tid; idx < 32*176; idx += NTHREADS) {
        int l = idx / 176, em = idx % 176;
        int slot = em >> 4, m = em & 15;
        sm.awT[l*MSTR + em] = add_w[((size_t)sm.elist[slot]*LB + l)*MB + m];
    }
    for (int idx = tid; idx < 176; idx += NTHREADS) {
        int slot = idx >> 4, m = idx & 15;
        sm.mb[idx] = mean_b[sm.elist[slot]*MB + m];
    }
    for (int idx = tid; idx < 32*32; idx += NTHREADS) {
        int o = idx >> 5, i = idx & 31;
        sm.gsw2[o*36 + i] = gsw[((size_t)r*LB + o)*LB + i];
        sm.gcw2[o*36 + i] = gcw[((size_t)r*LB + o)*LB + i];
    }
    if (tid < 32) sm.gsb[tid] = gsb_g[r*LB + tid];
    for (int idx = tid; idx < 64*64; idx += NTHREADS) {
        int o = idx >> 6, i = idx & 63;
        sm.lw2[o*68 + i] = lw[((size_t)r*HFB + o)*(2*LB) + i];
    }
    if (tid < 64) sm.lbS[tid] = lb_g[r*HFB + tid];
    for (int idx = tid; idx < 32*64; idx += NTHREADS) {
        int l = idx >> 6, i = idx & 63;
        sm.ow2[l*68 + i] = ow[((size_t)r*LB + l)*HFB + i];
    }
    if (tid < 32) sm.obS[tid] = ob_g[r*LB + tid];
    for (int idx = tid; idx < 96*32; idx += NTHREADS) {
        int j = idx >> 5, i = idx & 31;
        sm.wih2[j*36 + i] = wih[((size_t)r*96 + j)*LB + i];
        sm.whh2[j*36 + i] = whh[((size_t)r*96 + j)*HHB + i];
    }
    if (tid < 96) { sm.bihS[tid] = bih_g[r*96 + tid]; sm.bhhS[tid] = bhh_g[r*96 + tid]; }

    // ---- init state ----
    for (int idx = tid; idx < NB_PER*RB*LB; idx += NTHREADS) {
        int bb = idx / (RB*LB); int rem = idx % (RB*LB);
        int rr = rem >> 5, i = rem & 31;
        sm.zsD[0][bb*ZSTR + rr*36 + i] = z0[((size_t)(b0+bb)*RB + rr)*LB + i];
    }
    for (int idx = tid; idx < NB_PER*HHB; idx += NTHREADS) {
        int bb = idx >> 5, j = idx & 31;
        sm.hgT[bb*ISTR + j] = h0[((size_t)(b0+bb)*RB + r)*HHB + j];
    }
    __syncthreads();
    cluster_sync_all();

    const int w    = tid >> 5;          // warp 0..7
    const int lane = tid & 31;
    const int osub = lane >> 3;         // 0..3
    const int b    = lane & 7;          // batch slot 0..7

    // ---- DSMEM deltas ----
    const uint32_t smem_base = smem_u32(smraw);
    uint32_t pdelta[11];
    #pragma unroll
    for (int k = 0; k < 11; k++) {
        uint32_t prank = (uint32_t)(k + (k >= r ? 1 : 0));
        pdelta[k] = mapa_rank(smem_base, prank) - smem_base;
    }
    uint32_t laneDelta = 0u;
    #pragma unroll
    for (int k = 0; k < 11; k++)
        if (lane == k) laneDelta = pdelta[k];
    const uint32_t mbar_base = smem_u32(&sm.mbar[0]);
    const uint32_t zoff0 = smem_u32(&sm.zsD[0][0]);
    const uint32_t zoff1 = smem_u32(&sm.zsD[1][0]);

    const int row0 = 4*w + osub;        // lane's primary output row
    const int rowB = row0 + 32;

    for (int t = 0; t < T; t++) {
        const int buf = t & 1;
        const float* zb = &sm.zsD[buf][b*ZSTR];

        // ============ S0: own-state precompute (no peer deps) ============
        float gspart, lwz0, lwz1, gh0, gh1, gh2;
        {
            float4 za[8];
            const float4* zp = (const float4*)&zb[r*36];
            #pragma unroll
            for (int q = 0; q < 8; q++) za[q] = zp[q];

            float a0 = sm.gsb[row0], a1 = 0.f;
            const float4* wg = (const float4*)&sm.gsw2[row0*36];
            DOT32(a0, a1, wg, za);
            gspart = a0 + a1;

            float b0a = sm.lbS[row0], b1a = 0.f;
            const float4* wl0 = (const float4*)&sm.lw2[row0*68];
            DOT32(b0a, b1a, wl0, za);
            lwz0 = b0a + b1a;

            float c0 = sm.lbS[rowB], c1 = 0.f;
            const float4* wl1 = (const float4*)&sm.lw2[rowB*68];
            DOT32(c0, c1, wl1, za);
            lwz1 = c0 + c1;
        }
        {
            float4 ha[8];
            const float4* hp = (const float4*)&sm.hgT[b*ISTR];
            #pragma unroll
            for (int q = 0; q < 8; q++) ha[q] = hp[q];

            float a0 = sm.bhhS[row0], a1 = 0.f;
            float b0a = sm.bhhS[row0+32], b1a = 0.f;
            float c0 = sm.bhhS[row0+64], c1 = 0.f;
            const float4* w0 = (const float4*)&sm.whh2[(row0   )*36];
            const float4* w1 = (const float4*)&sm.whh2[(row0+32)*36];
            const float4* w2 = (const float4*)&sm.whh2[(row0+64)*36];
            #pragma unroll
            for (int q = 0; q < 8; q++) {
                float4 a = ha[q];
                float4 x0 = w0[q], x1 = w1[q], x2 = w2[q];
                a0  = fmaf(x0.x, a.x, a0 ); a1  = fmaf(x0.y, a.y, a1 );
                a0  = fmaf(x0.z, a.z, a0 ); a1  = fmaf(x0.w, a.w, a1 );
                b0a = fmaf(x1.x, a.x, b0a); b1a = fmaf(x1.y, a.y, b1a);
                b0a = fmaf(x1.z, a.z, b0a); b1a = fmaf(x1.w, a.w, b1a);
                c0  = fmaf(x2.x, a.x, c0 ); c1  = fmaf(x2.y, a.y, c1 );
                c0  = fmaf(x2.z, a.z, c0 ); c1  = fmaf(x2.w, a.w, c1 );
            }
            gh0 = a0 + a1; gh1 = b0a + b1a; gh2 = c0 + c1;
        }

        // ============ wait for peers' z(t-1) ============
        if (t > 0)
            mbar_wait(mbar_base + (uint32_t)(((t - 1) & 1) * 8),
                      (uint32_t)(((t - 1) >> 1) & 1));

        // ============ S1: edge means; store ms inline ============
        #pragma unroll
        for (int k = 0; k < 6; k++) {
            const int q = w + 8*k;
            if (q < 44) {
                const int row = 4*q + osub;
                const int slot = row >> 4;
                const int s = sm.slist[slot];
                const float4* ap = (const float4*)&zb[s*36];
                const float4* wp = (const float4*)&sm.mw2[row*36];
                float a0 = sm.mb[row], a1 = 0.f;
                DOT32(a0, a1, wp, ap);
                const float mv = a0 + a1;
                sm.meanT[b*MSTR + row] = mv;
                ms[((size_t)(b0 + b)*T + t)*(EB*MB)
                   + (size_t)sm.elist[slot]*MB + (row & 15)] = mv;
            }
        }
        __syncthreads();   // meanT complete

        // ============ S2: projection -> inc (176-dot) ============
        {
            const float4* ap = (const float4*)&sm.meanT[b*MSTR];
            const float4* wp = (const float4*)&sm.awT[row0*MSTR];
            float a0 = 0.f, a1 = 0.f, a2 = 0.f, a3 = 0.f;
            #pragma unroll
            for (int q = 0; q < 44; q++) {
                float4 x = wp[q], a = ap[q];
                a0 = fmaf(x.x, a.x, a0); a1 = fmaf(x.y, a.y, a1);
                a2 = fmaf(x.z, a.z, a2); a3 = fmaf(x.w, a.w, a3);
            }
            sm.incT[b*ISTR + row0] = (a0 + a1) + (a2 + a3);
        }
        __syncthreads();   // incT complete

        // ============ S3: inc consumers + register-local GRU ============
        float gate;
        {
            float4 ia[8];
            const float4* ip = (const float4*)&sm.incT[b*ISTR];
            #pragma unroll
            for (int q = 0; q < 8; q++) ia[q] = ip[q];

            float a0 = gspart, a1 = 0.f;
            const float4* wg = (const float4*)&sm.gcw2[row0*36];
            DOT32(a0, a1, wg, ia);
            gate = fsig(a0 + a1);

            float v0a = lwz0, v0b = 0.f;
            const float4* wl0 = (const float4*)&sm.lw2[row0*68 + 32];
            DOT32(v0a, v0b, wl0, ia);
            const float v0 = v0a + v0b;
            sm.hbufT[b*HSTR + row0] = v0 * fsig(v0);

            float v1a = lwz1, v1b = 0.f;
            const float4* wl1 = (const float4*)&sm.lw2[rowB*68 + 32];
            DOT32(v1a, v1b, wl1, ia);
            const float v1 = v1a + v1b;
            sm.hbufT[b*HSTR + rowB] = v1 * fsig(v1);

            // GRU: all three gi rows belong to this lane's (row0, b)
            float g0a = sm.bihS[row0],    g0b = 0.f;
            float g1a = sm.bihS[row0+32], g1b = 0.f;
            float g2a = sm.bihS[row0+64], g2b = 0.f;
            const float4* w0 = (const float4*)&sm.wih2[(row0   )*36];
            const float4* w1 = (const float4*)&sm.wih2[(row0+32)*36];
            const float4* w2 = (const float4*)&sm.wih2[(row0+64)*36];
            #pragma unroll
            for (int q = 0; q < 8; q++) {
                float4 a = ia[q];
                float4 x0 = w0[q], x1 = w1[q], x2 = w2[q];
                g0a = fmaf(x0.x, a.x, g0a); g0b = fmaf(x0.y, a.y, g0b);
                g0a = fmaf(x0.z, a.z, g0a); g0b = fmaf(x0.w, a.w, g0b);
                g1a = fmaf(x1.x, a.x, g1a); g1b = fmaf(x1.y, a.y, g1b);
                g1a = fmaf(x1.z, a.z, g1a); g1b = fmaf(x1.w, a.w, g1b);
                g2a = fmaf(x2.x, a.x, g2a); g2b = fmaf(x2.y, a.y, g2b);
                g2a = fmaf(x2.z, a.z, g2a); g2b = fmaf(x2.w, a.w, g2b);
            }
            const float gr = fsig((g0a + g0b) + gh0);
            const float gz = fsig((g1a + g1b) + gh1);
            const float nn = tanhf(fmaf(gr, gh2, g2a + g2b));
            const float hold = sm.hgT[b*ISTR + row0];
            sm.hgT[b*ISTR + row0] = (1.0f - gz)*nn + gz*hold;
        }
        __syncthreads();   // hbufT + hgT complete

        // ============ S4: out layer, z update, publish ============
        {
            const float4* ap = (const float4*)&sm.hbufT[b*HSTR];
            const float4* wp = (const float4*)&sm.ow2[row0*68];
            float a0 = sm.obS[row0], a1 = 0.f, a2 = 0.f, a3 = 0.f;
            #pragma unroll
            for (int q = 0; q < 16; q++) {
                float4 x = wp[q], a = ap[q];
                a0 = fmaf(x.x, a.x, a0); a1 = fmaf(x.y, a.y, a1);
                a2 = fmaf(x.z, a.z, a2); a3 = fmaf(x.w, a.w, a3);
            }
            const float target = tanhf((a0 + a1) + (a2 + a3));
            const int zidx = b*ZSTR + r*36 + row0;
            const float zold = sm.zsD[buf][zidx];
            const float znew = fmaf(0.1f * gate, target - zold, zold);

            sm.zsD[buf ^ 1][zidx] = znew;
            const uint32_t zaddr = (buf ? zoff0 : zoff1) + 4u*(uint32_t)zidx;
            #pragma unroll
            for (int k = 0; k < 11; k++)
                st_remote_f32(zaddr + pdelta[k], znew);
            zt[(((size_t)(b0 + b)*T + t)*RB + r)*LB + row0] = znew;
            __syncwarp();
            if (lane < 11)
                mbar_arrive_remote(mbar_base + (uint32_t)((t & 1) * 8) + laneDelta);
        }
        __syncthreads();   // local zsD[nxt] ready for next S0
    }

    // final h: warp w stores batch w
    hf[((size_t)(b0 + w)*RB + r)*HHB + lane] = sm.hgT[w*ISTR + lane];

    __syncthreads();
    cluster_sync_all();   // peers may still be writing our smem
}

extern "C" void kernel_launch(void* const* d_in, const int* in_sizes, int n_in,
                              void* d_out, int out_size) {
    const float* z0     = (const float*)d_in[0];
    const float* h0     = (const float*)d_in[1];
    const float* mean_w = (const float*)d_in[2];
    const float* mean_b = (const float*)d_in[3];
    const float* add_w  = (const float*)d_in[4];
    const float* gsw    = (const float*)d_in[5];
    const float* gsb    = (const float*)d_in[6];
    const float* gcw    = (const float*)d_in[7];
    const float* lw     = (const float*)d_in[8];
    const float* lb     = (const float*)d_in[9];
    const float* ow     = (const float*)d_in[10];
    const float* ob     = (const float*)d_in[11];
    const float* wih    = (const float*)d_in[12];
    const float* whh    = (const float*)d_in[13];
    const float* bih    = (const float*)d_in[14];
    const float* bhh    = (const float*)d_in[15];
    const int* src_idx  = (const int*)d_in[16];
    const int* tgt_idx  = (const int*)d_in[17];
    // out_size = B*T*R*L + B*R*Hh + B*T*E*M
    const int per_t = BTOT*RB*LB + BTOT*EB*MB;
    const int T = (out_size - BTOT*RB*HHB) / per_t;

    float* out = (float*)d_out;
    float* zt = out;
    float* hf = zt + (size_t)BTOT * T * RB * LB;
    float* ms = hf + (size_t)BTOT * RB * HHB;

    cudaFuncSetAttribute(nv_main_kernel,
                         cudaFuncAttributeMaxDynamicSharedMemorySize,
                         (int)sizeof(SmemLayout));
    cudaFuncSetAttribute(nv_main_kernel,
                         cudaFuncAttributeNonPortableClusterSizeAllowed, 1);

    nv_main_kernel<<<NBLOCKS, NTHREADS, sizeof(SmemLayout)>>>(
        z0, h0, mean_w, mean_b, add_w, gsw, gsb, gcw, lw, lb, ow, ob,
        wih, whh, bih, bhh, src_idx, tgt_idx, T, zt, hf, ms);
}

// round 8
// speedup vs baseline: 1.0928x; 1.0928x over previous
#include <cuda_runtime.h>
#include <cstddef>
#include <cstdint>

// Problem constants (fixed by setup_inputs)
#define RB   12
#define LB   32
#define MB   16
#define HHB  32
#define HFB  64
#define EB   132
#define BTOT 64
#define NB_PER 8
#define NGROUP (BTOT/NB_PER)
#define NBLOCKS (NGROUP*RB)   // 96 blocks = 8 clusters of 12
#define NTHREADS 512          // 16 warps: 8 compute + 8 epilogue

struct __align__(16) SmemLayout {
    unsigned long long mbar[2];
    // weights, row-per-output, padded strides (conflict-free LDS.128)
    float mw2[176*36];     // [(slot*16+m)][k] stride 36 fl (144B)
    float aw2[11*32*20];   // [slot*32+l][m] stride 20 fl (80B)
    float mb [176];
    float gsw2[32*36];
    float gcw2[32*36];
    float gsb[32];
    float lw2[64*68];      // [o][i0..63] stride 68 fl (272B)
    float lbS[64];
    float ow2[32*68];      // [l][hf]
    float obS[32];
    float wih2[96*36];
    float whh2[96*36];
    float bihS[96];
    float bhhS[96];
    // activations
    float zsD [2][NB_PER][RB][LB];   // DSMEM-exchanged z (double buffer)
    float meanF[3][NB_PER][192];     // per-step means (176 used), triple buffer
    float incD [3][NB_PER][LB];
    float zpub [3][NB_PER][LB];
    float hbufT[NB_PER][HFB];
    float hgS  [NB_PER][HHB];
    int   elist[12];
    int   slist[12];
};

__device__ __forceinline__ float fsig(float x) { return 1.0f / (1.0f + __expf(-x)); }

__device__ __forceinline__ uint32_t smem_u32(const void* p) {
    uint32_t a;
    asm("{ .reg .u64 t; cvta.to.shared.u64 t, %1; cvt.u32.u64 %0, t; }"
        : "=r"(a) : "l"(p));
    return a;
}
__device__ __forceinline__ uint32_t mapa_rank(uint32_t laddr, uint32_t rank) {
    uint32_t r;
    asm("mapa.shared::cluster.u32 %0, %1, %2;" : "=r"(r) : "r"(laddr), "r"(rank));
    return r;
}
__device__ __forceinline__ void st_remote_f32(uint32_t addr, float v) {
    asm volatile("st.shared::cluster.f32 [%0], %1;" :: "r"(addr), "f"(v) : "memory");
}
__device__ __forceinline__ void mbar_arrive_remote(uint32_t addr) {
    asm volatile("mbarrier.arrive.release.cluster.shared::cluster.b64 _, [%0];"
                 :: "r"(addr) : "memory");
}
__device__ __forceinline__ void mbar_init(uint32_t addr, uint32_t cnt) {
    asm volatile("mbarrier.init.shared.b64 [%0], %1;" :: "r"(addr), "r"(cnt) : "memory");
}
__device__ __forceinline__ void mbar_wait(uint32_t addr, uint32_t parity) {
    uint32_t done;
    do {
        asm volatile(
            "{\n\t.reg .pred p;\n\t"
            "mbarrier.try_wait.parity.acquire.cluster.shared::cta.b64 p, [%1], %2, 0x989680;\n\t"
            "selp.b32 %0, 1, 0, p;\n\t}"
            : "=r"(done) : "r"(addr), "r"(parity) : "memory");
    } while (!done);
}
__device__ __forceinline__ void cluster_sync_all() {
    asm volatile("barrier.cluster.arrive.aligned;" ::: "memory");
    asm volatile("barrier.cluster.wait.aligned;" ::: "memory");
}
__device__ __forceinline__ void bar_sync64(int id) {
    asm volatile("bar.sync %0, 64;" :: "r"(id) : "memory");
}
__device__ __forceinline__ void bar_arrive64(int id) {
    asm volatile("bar.arrive %0, 64;" :: "r"(id) : "memory");
}

// ---- packed f32x2 helpers ----
__device__ __forceinline__ void lds2(unsigned long long& x, unsigned long long& y, uint32_t a) {
    asm volatile("ld.shared.v2.u64 {%0, %1}, [%2];" : "=l"(x), "=l"(y) : "r"(a));
}
__device__ __forceinline__ void fma2(unsigned long long& d, unsigned long long a, unsigned long long b) {
    asm volatile("fma.rn.f32x2 %0, %1, %2, %0;" : "+l"(d) : "l"(a), "l"(b));
}
__device__ __forceinline__ unsigned long long pack2(float x, float y) {
    unsigned long long r;
    asm("mov.b64 %0, {%1, %2};" : "=l"(r) : "f"(x), "f"(y));
    return r;
}
__device__ __forceinline__ float hsum2(unsigned long long v) {
    float lo, hi;
    asm("mov.b64 {%0, %1}, %2;" : "=f"(lo), "=f"(hi) : "l"(v));
    return lo + hi;
}

// packed dot over N*8 floats: weights (distinct rows) + activations (broadcast)
#define DOTP(accA, accB, WADDR, AADDR, NITER)                         \
    {                                                                 \
        _Pragma("unroll")                                             \
        for (int _q = 0; _q < (NITER); _q++) {                        \
            unsigned long long _wx, _wy, _ax, _ay;                    \
            lds2(_wx, _wy, (WADDR) + 16u*_q);                         \
            lds2(_ax, _ay, (AADDR) + 16u*_q);                         \
            fma2(accA, _wx, _ax); fma2(accB, _wy, _ay);               \
        }                                                             \
    }

// scalar dot-32 (epilogue warps)
#define DOT32(acc0, acc1, WP, AP)                                    \
    {                                                                \
        _Pragma("unroll")                                            \
        for (int q = 0; q < 8; q++) {                                \
            float4 x = (WP)[q], a = (AP)[q];                         \
            acc0 = fmaf(x.x, a.x, acc0); acc1 = fmaf(x.y, a.y, acc1);\
            acc0 = fmaf(x.z, a.z, acc0); acc1 = fmaf(x.w, a.w, acc1);\
        }                                                            \
    }

__global__ void __launch_bounds__(NTHREADS, 1) __cluster_dims__(RB, 1, 1)
nv_main_kernel(
    const float* __restrict__ z0,  const float* __restrict__ h0,
    const float* __restrict__ mean_w, const float* __restrict__ mean_b,
    const float* __restrict__ add_w,
    const float* __restrict__ gsw, const float* __restrict__ gsb_g,
    const float* __restrict__ gcw,
    const float* __restrict__ lw,  const float* __restrict__ lb_g,
    const float* __restrict__ ow,  const float* __restrict__ ob_g,
    const float* __restrict__ wih, const float* __restrict__ whh,
    const float* __restrict__ bih_g, const float* __restrict__ bhh_g,
    const int* __restrict__ src_idx, const int* __restrict__ tgt_idx,
    int T,
    float* __restrict__ zt, float* __restrict__ hf, float* __restrict__ ms)
{
    extern __shared__ char smraw[];
    SmemLayout& sm = *reinterpret_cast<SmemLayout*>(smraw);
    const int tid = threadIdx.x;
    const int g = blockIdx.x / RB;
    const int r = blockIdx.x % RB;
    const int b0 = g * NB_PER;

    // ---- incoming-edge list ----
    for (int e = tid; e < EB; e += NTHREADS) {
        if (tgt_idx[e] == r) {
            int s = src_idx[e];
            int slot = (s < r) ? s : s - 1;
            sm.elist[slot] = e;
            sm.slist[slot] = s;
        }
    }
    if (tid < 2) mbar_init(smem_u32(&sm.mbar[tid]), 88);
    __syncthreads();

    // ---- cache weights ----
    for (int idx = tid; idx < 176*32; idx += NTHREADS) {
        int row = idx >> 5, k = idx & 31;
        int slot = row >> 4, m = row & 15;
        sm.mw2[row*36 + k] = mean_w[((size_t)sm.elist[slot]*MB + m)*LB + k];
    }
    for (int idx = tid; idx < 11*32*16; idx += NTHREADS) {
        int row = idx >> 4, m = idx & 15;           // row = slot*32 + l
        int slot = row >> 5, l = row & 31;
        sm.aw2[row*20 + m] = add_w[((size_t)sm.elist[slot]*LB + l)*MB + m];
    }
    for (int idx = tid; idx < 176; idx += NTHREADS) {
        int slot = idx >> 4, m = idx & 15;
        sm.mb[idx] = mean_b[sm.elist[slot]*MB + m];
    }
    for (int idx = tid; idx < 32*32; idx += NTHREADS) {
        int o = idx >> 5, i = idx & 31;
        sm.gsw2[o*36 + i] = gsw[((size_t)r*LB + o)*LB + i];
        sm.gcw2[o*36 + i] = gcw[((size_t)r*LB + o)*LB + i];
    }
    if (tid < 32) sm.gsb[tid] = gsb_g[r*LB + tid];
    for (int idx = tid; idx < 64*64; idx += NTHREADS) {
        int o = idx >> 6, i = idx & 63;
        sm.lw2[o*68 + i] = lw[((size_t)r*HFB + o)*(2*LB) + i];
    }
    if (tid < 64) sm.lbS[tid] = lb_g[r*HFB + tid];
    for (int idx = tid; idx < 32*64; idx += NTHREADS) {
        int l = idx >> 6, i = idx & 63;
        sm.ow2[l*68 + i] = ow[((size_t)r*LB + l)*HFB + i];
    }
    if (tid < 32) sm.obS[tid] = ob_g[r*LB + tid];
    for (int idx = tid; idx < 96*32; idx += NTHREADS) {
        int j = idx >> 5, i = idx & 31;
        sm.wih2[j*36 + i] = wih[((size_t)r*96 + j)*LB + i];
        sm.whh2[j*36 + i] = whh[((size_t)r*96 + j)*HHB + i];
    }
    if (tid < 96) { sm.bihS[tid] = bih_g[r*96 + tid]; sm.bhhS[tid] = bhh_g[r*96 + tid]; }

    // ---- init state ----
    for (int idx = tid; idx < NB_PER*RB*LB; idx += NTHREADS) {
        int bb = idx / (RB*LB); int rem = idx % (RB*LB);
        int rr = rem >> 5, i = rem & 31;
        sm.zsD[0][bb][rr][i] = z0[((size_t)(b0+bb)*RB + rr)*LB + i];
    }
    for (int idx = tid; idx < NB_PER*HHB; idx += NTHREADS) {
        int bb = idx >> 5, j = idx & 31;
        sm.hgS[bb][j] = h0[((size_t)(b0+bb)*RB + r)*HHB + j];
    }
    __syncthreads();
    cluster_sync_all();

    const int w    = tid >> 5;          // 0..15
    const int lane = tid & 31;

    if (w < 8) {
        // =================== COMPUTE WARP: batch w ===================
        const int p = w;
        const int SIG = 2*p, ACK = 2*p + 1;
        const int sub = lane >> 4, m16 = lane & 15;

        const uint32_t smem_base = smem_u32(smraw);
        uint32_t pdelta[11];
        #pragma unroll
        for (int k = 0; k < 11; k++) {
            uint32_t prank = (uint32_t)(k + (k >= r ? 1 : 0));
            pdelta[k] = mapa_rank(smem_base, prank) - smem_base;
        }
        uint32_t laneDelta = 0u;
        #pragma unroll
        for (int k = 0; k < 11; k++)
            if (lane == k) laneDelta = pdelta[k];
        const uint32_t mbar_base = smem_u32(&sm.mbar[0]);

        const uint32_t zsD_base = smem_u32(&sm.zsD[0][p][0][0]);  // + buf*49152... no:
        // zsD[2][8][12][32]: [buf][p] offset = (buf*8+p)*12*32*4 = (buf*8+p)*1536
        const uint32_t zsD0 = smem_u32(&sm.zsD[0][0][0][0]);
        const uint32_t mw_base  = smem_u32(&sm.mw2[0]);
        const uint32_t aw_base  = smem_u32(&sm.aw2[0]);
        const uint32_t gsw_base = smem_u32(&sm.gsw2[0]) + (uint32_t)(lane*144);
        const uint32_t gcw_base = smem_u32(&sm.gcw2[0]) + (uint32_t)(lane*144);
        const uint32_t lw_r0    = smem_u32(&sm.lw2[0]) + (uint32_t)(lane*272);
        const uint32_t lw_r1    = smem_u32(&sm.lw2[0]) + (uint32_t)((lane+32)*272);
        const uint32_t ow_base  = smem_u32(&sm.ow2[0]) + (uint32_t)(lane*272);
        const uint32_t hbuf_addr = smem_u32(&sm.hbufT[p][0]);
        (void)zsD_base;

        int buf3 = 0;
        for (int t = 0; t < T; t++) {
            if (t >= 2) bar_sync64(ACK);     // epi finished step t-2
            const int buf = t & 1;
            const uint32_t zw_base = zsD0 + (uint32_t)((buf*8 + p)*1536);
            const uint32_t zr_addr = zw_base + (uint32_t)(r*128);

            // ---- S0: own-state dots (packed) ----
            float gspart, lwz0, lwz1;
            {
                unsigned long long A = 0ull, B = 0ull;
                DOTP(A, B, gsw_base, zr_addr, 8);
                gspart = sm.gsb[lane] + hsum2(A) + hsum2(B);
            }
            {
                unsigned long long A = 0ull, B = 0ull;
                DOTP(A, B, lw_r0, zr_addr, 8);
                lwz0 = sm.lbS[lane] + hsum2(A) + hsum2(B);
            }
            {
                unsigned long long A = 0ull, B = 0ull;
                DOTP(A, B, lw_r1, zr_addr, 8);
                lwz1 = sm.lbS[lane + 32] + hsum2(A) + hsum2(B);
            }

            // ---- wait peers' z(t-1) ----
            if (t > 0)
                mbar_wait(mbar_base + (uint32_t)(((t - 1) & 1) * 8),
                          (uint32_t)(((t - 1) >> 1) & 1));

            // ---- S1: means + projection ----
            const uint32_t meanRow = smem_u32(&sm.meanF[buf3][p][0]);
            unsigned long long pA = 0ull, pB = 0ull;
            #pragma unroll
            for (int rd = 0; rd < 6; rd++) {
                const int base = 2*rd;
                const int eslot = base + sub;
                if (eslot < 11) {
                    const int s = sm.slist[eslot];
                    const int row = eslot*16 + m16;
                    unsigned long long A = pack2(sm.mb[row], 0.f), B = 0ull;
                    DOTP(A, B, mw_base + (uint32_t)(row*144),
                               zw_base + (uint32_t)(s*128), 8);
                    sm.meanF[buf3][p][row] = hsum2(A) + hsum2(B);
                }
                __syncwarp();
                const int n2 = (base + 1 < 11) ? 2 : 1;
                for (int ss = 0; ss < n2; ss++) {
                    const int sl = base + ss;
                    DOTP(pA, pB, aw_base + (uint32_t)((sl*32 + lane)*80),
                                 meanRow + (uint32_t)(sl*64), 4);
                }
                __syncwarp();
            }
            sm.incD[buf3][p][lane] = hsum2(pA) + hsum2(pB);
            __syncwarp();
            const uint32_t inc_addr = smem_u32(&sm.incD[buf3][p][0]);

            // ---- S2: gate + hidden inc-half + silu ----
            float gate;
            {
                unsigned long long A = 0ull, B = 0ull;
                DOTP(A, B, gcw_base, inc_addr, 8);
                gate = fsig(gspart + hsum2(A) + hsum2(B));
            }
            {
                unsigned long long A = 0ull, B = 0ull;
                DOTP(A, B, lw_r0 + 128u, inc_addr, 8);
                const float v = lwz0 + hsum2(A) + hsum2(B);
                sm.hbufT[p][lane] = v * fsig(v);
            }
            {
                unsigned long long A = 0ull, B = 0ull;
                DOTP(A, B, lw_r1 + 128u, inc_addr, 8);
                const float v = lwz1 + hsum2(A) + hsum2(B);
                sm.hbufT[p][lane + 32] = v * fsig(v);
            }
            __syncwarp();

            // ---- S3: out layer + z update + publish ----
            {
                unsigned long long A = 0ull, B = 0ull;
                DOTP(A, B, ow_base, hbuf_addr, 16);
                const float target = tanhf(sm.obS[lane] + hsum2(A) + hsum2(B));
                const float zold = sm.zsD[buf][p][r][lane];
                const float znew = fmaf(0.1f * gate, target - zold, zold);

                const int nxt = buf ^ 1;
                sm.zsD[nxt][p][r][lane] = znew;
                sm.zpub[buf3][p][lane]  = znew;
                const uint32_t zaddr = smem_base +
                    (uint32_t)((const char*)&sm.zsD[nxt][p][r][lane] - (const char*)&sm);
                #pragma unroll
                for (int k = 0; k < 11; k++)
                    st_remote_f32(zaddr + pdelta[k], znew);
                __syncwarp();
                if (lane < 11)
                    mbar_arrive_remote(mbar_base + (uint32_t)((t & 1) * 8) + laneDelta);
            }
            bar_arrive64(SIG);               // step-t data ready for epilogue

            buf3 = (buf3 == 2) ? 0 : buf3 + 1;
        }
    } else {
        // =================== EPILOGUE WARP: batch p = w-8 ===================
        const int p = w - 8;
        const int SIG = 2*p, ACK = 2*p + 1;
        float hnew = 0.0f;

        int buf3 = 0;
        for (int t = 0; t < T; t++) {
            // whh dots on own h (pre-SIG)
            float gh0, gh1, gh2;
            {
                const float4* hp = (const float4*)&sm.hgS[p][0];
                float4 ha[8];
                #pragma unroll
                for (int q = 0; q < 8; q++) ha[q] = hp[q];
                float a0 = sm.bhhS[lane],    a1 = 0.f;
                float b0a = sm.bhhS[lane+32], b1a = 0.f;
                float c0 = sm.bhhS[lane+64], c1 = 0.f;
                const float4* w0 = (const float4*)&sm.whh2[(lane   )*36];
                const float4* w1 = (const float4*)&sm.whh2[(lane+32)*36];
                const float4* w2 = (const float4*)&sm.whh2[(lane+64)*36];
                #pragma unroll
                for (int q = 0; q < 8; q++) {
                    float4 a = ha[q];
                    float4 x0 = w0[q], x1 = w1[q], x2 = w2[q];
                    a0  = fmaf(x0.x, a.x, a0 ); a1  = fmaf(x0.y, a.y, a1 );
                    a0  = fmaf(x0.z, a.z, a0 ); a1  = fmaf(x0.w, a.w, a1 );
                    b0a = fmaf(x1.x, a.x, b0a); b1a = fmaf(x1.y, a.y, b1a);
                    b0a = fmaf(x1.z, a.z, b0a); b1a = fmaf(x1.w, a.w, b1a);
                    c0  = fmaf(x2.x, a.x, c0 ); c1  = fmaf(x2.y, a.y, c1 );
                    c0  = fmaf(x2.z, a.z, c0 ); c1  = fmaf(x2.w, a.w, c1 );
                }
                gh0 = a0 + a1; gh1 = b0a + b1a; gh2 = c0 + c1;
            }

            bar_sync64(SIG);                 // compute published step t

            // wih dots + GRU
            {
                const float4* ip = (const float4*)&sm.incD[buf3][p][0];
                float4 ia[8];
                #pragma unroll
                for (int q = 0; q < 8; q++) ia[q] = ip[q];
                float g0a = sm.bihS[lane],    g0b = 0.f;
                float g1a = sm.bihS[lane+32], g1b = 0.f;
                float g2a = sm.bihS[lane+64], g2b = 0.f;
                const float4* w0 = (const float4*)&sm.wih2[(lane   )*36];
                const float4* w1 = (const float4*)&sm.wih2[(lane+32)*36];
                const float4* w2 = (const float4*)&sm.wih2[(lane+64)*36];
                #pragma unroll
                for (int q = 0; q < 8; q++) {
                    float4 a = ia[q];
                    float4 x0 = w0[q], x1 = w1[q], x2 = w2[q];
                    g0a = fmaf(x0.x, a.x, g0a); g0b = fmaf(x0.y, a.y, g0b);
                    g0a = fmaf(x0.z, a.z, g0a); g0b = fmaf(x0.w, a.w, g0b);
                    g1a = fmaf(x1.x, a.x, g1a); g1b = fmaf(x1.y, a.y, g1b);
                    g1a = fmaf(x1.z, a.z, g1a); g1b = fmaf(x1.w, a.w, g1b);
                    g2a = fmaf(x2.x, a.x, g2a); g2b = fmaf(x2.y, a.y, g2b);
                    g2a = fmaf(x2.z, a.z, g2a); g2b = fmaf(x2.w, a.w, g2b);
                }
                const float gr = fsig((g0a + g0b) + gh0);
                const float gz = fsig((g1a + g1b) + gh1);
                const float nn = tanhf(fmaf(gr, gh2, g2a + g2b));
                const float hold = sm.hgS[p][lane];
                hnew = (1.0f - gz)*nn + gz*hold;
                sm.hgS[p][lane] = hnew;
            }
            __syncwarp();

            // global stores (zt, ms)
            zt[(((size_t)(b0 + p)*T + t)*RB + r)*LB + lane] = sm.zpub[buf3][p][lane];
            {
                float* msrow = ms + ((size_t)(b0 + p)*T + t)*(EB*MB);
                #pragma unroll
                for (int j = 0; j < 6; j++) {
                    const int idx = j*32 + lane;
                    if (idx < 176)
                        msrow[sm.elist[idx >> 4]*MB + (idx & 15)] = sm.meanF[buf3][p][idx];
                }
            }

            if (t < T - 2) bar_arrive64(ACK);
            buf3 = (buf3 == 2) ? 0 : buf3 + 1;
        }

        hf[((size_t)(b0 + p)*RB + r)*HHB + lane] = hnew;
    }

    cluster_sync_all();   // peers may still be writing our smem
}

extern "C" void kernel_launch(void* const* d_in, const int* in_sizes, int n_in,
                              void* d_out, int out_size) {
    const float* z0     = (const float*)d_in[0];
    const float* h0     = (const float*)d_in[1];
    const float* mean_w = (const float*)d_in[2];
    const float* mean_b = (const float*)d_in[3];
    const float* add_w  = (const float*)d_in[4];
    const float* gsw    = (const float*)d_in[5];
    const float* gsb    = (const float*)d_in[6];
    const float* gcw    = (const float*)d_in[7];
    const float* lw     = (const float*)d_in[8];
    const float* lb     = (const float*)d_in[9];
    const float* ow     = (const float*)d_in[10];
    const float* ob     = (const float*)d_in[11];
    const float* wih    = (const float*)d_in[12];
    const float* whh    = (const float*)d_in[13];
    const float* bih    = (const float*)d_in[14];
    const float* bhh    = (const float*)d_in[15];
    const int* src_idx  = (const int*)d_in[16];
    const int* tgt_idx  = (const int*)d_in[17];
    // out_size = B*T*R*L + B*R*Hh + B*T*E*M
    const int per_t = BTOT*RB*LB + BTOT*EB*MB;
    const int T = (out_size - BTOT*RB*HHB) / per_t;

    float* out = (float*)d_out;
    float* zt = out;
    float* hf = zt + (size_t)BTOT * T * RB * LB;
    float* ms = hf + (size_t)BTOT * RB * HHB;

    cudaFuncSetAttribute(nv_main_kernel,
                         cudaFuncAttributeMaxDynamicSharedMemorySize,
                         (int)sizeof(SmemLayout));
    cudaFuncSetAttribute(nv_main_kernel,
                         cudaFuncAttributeNonPortableClusterSizeAllowed, 1);

    nv_main_kernel<<<NBLOCKS, NTHREADS, sizeof(SmemLayout)>>>(
        z0, h0, mean_w, mean_b, add_w, gsw, gsb, gcw, lw, lb, ow, ob,
        wih, whh, bih, bhh, src_idx, tgt_idx, T, zt, hf, ms);
}

// round 9
// speedup vs baseline: 1.1344x; 1.0381x over previous
#include <cuda_runtime.h>
#include <cstddef>
#include <cstdint>

// Problem constants (fixed by setup_inputs)
#define RB   12
#define LB   32
#define MB   16
#define HHB  32
#define HFB  64
#define EB   132
#define BTOT 64
#define NB_PER 8
#define NGROUP (BTOT/NB_PER)
#define NBLOCKS (NGROUP*RB)   // 96 blocks = 8 clusters of 12
#define NTHREADS 512          // 16 warps: 8 compute + 8 epilogue

struct __align__(16) SmemLayout {
    unsigned long long mbar[2];
    // weights, row-per-output, padded strides (conflict-free LDS.128)
    float mw2[176*36];     // [(slot*16+m)][k] stride 36
    float aw2[11*32*20];   // [slot*32+l][m] stride 20
    float mb [176];
    float gsw2[32*36];
    float gcw2[32*36];
    float gsb[32];
    float lw2[64*68];      // [o][i0..63] stride 68
    float lbS[64];
    float ow2[32*68];      // [l][hf]
    float obS[32];
    float wih2[96*36];
    float whh2[96*36];
    float bihS[96];
    float bhhS[96];
    // activations
    float zsD [2][NB_PER][RB][LB];   // DSMEM-exchanged z (double buffer)
    float meanF[3][NB_PER][192];     // per-step means (176 used), triple buffer
    float incD [3][NB_PER][LB];
    float zpub [3][NB_PER][LB];
    float hbufT[NB_PER][HFB];
    float hgS  [NB_PER][HHB];
    int   elist[12];
    int   slist[12];
};

__device__ __forceinline__ float fsig(float x) { return 1.0f / (1.0f + __expf(-x)); }

__device__ __forceinline__ uint32_t smem_u32(const void* p) {
    uint32_t a;
    asm("{ .reg .u64 t; cvta.to.shared.u64 t, %1; cvt.u32.u64 %0, t; }"
        : "=r"(a) : "l"(p));
    return a;
}
__device__ __forceinline__ uint32_t mapa_rank(uint32_t laddr, uint32_t rank) {
    uint32_t r;
    asm("mapa.shared::cluster.u32 %0, %1, %2;" : "=r"(r) : "r"(laddr), "r"(rank));
    return r;
}
__device__ __forceinline__ void st_remote_f32(uint32_t addr, float v) {
    asm volatile("st.shared::cluster.f32 [%0], %1;" :: "r"(addr), "f"(v) : "memory");
}
__device__ __forceinline__ void mbar_arrive_remote(uint32_t addr) {
    asm volatile("mbarrier.arrive.release.cluster.shared::cluster.b64 _, [%0];"
                 :: "r"(addr) : "memory");
}
__device__ __forceinline__ void mbar_init(uint32_t addr, uint32_t cnt) {
    asm volatile("mbarrier.init.shared.b64 [%0], %1;" :: "r"(addr), "r"(cnt) : "memory");
}
__device__ __forceinline__ void mbar_wait(uint32_t addr, uint32_t parity) {
    uint32_t done;
    do {
        asm volatile(
            "{\n\t.reg .pred p;\n\t"
            "mbarrier.try_wait.parity.acquire.cluster.shared::cta.b64 p, [%1], %2, 0x989680;\n\t"
            "selp.b32 %0, 1, 0, p;\n\t}"
            : "=r"(done) : "r"(addr), "r"(parity) : "memory");
    } while (!done);
}
__device__ __forceinline__ void cluster_sync_all() {
    asm volatile("barrier.cluster.arrive.aligned;" ::: "memory");
    asm volatile("barrier.cluster.wait.aligned;" ::: "memory");
}
__device__ __forceinline__ void bar_sync64(int id) {
    asm volatile("bar.sync %0, 64;" :: "r"(id) : "memory");
}
__device__ __forceinline__ void bar_arrive64(int id) {
    asm volatile("bar.arrive %0, 64;" :: "r"(id) : "memory");
}

// scalar dot-32 over float4: 2 accumulators
#define DOT32(acc0, acc1, WP, AP)                                    \
    {                                                                \
        _Pragma("unroll")                                            \
        for (int q = 0; q < 8; q++) {                                \
            float4 x = (WP)[q], a = (AP)[q];                         \
            acc0 = fmaf(x.x, a.x, acc0); acc1 = fmaf(x.y, a.y, acc1);\
            acc0 = fmaf(x.z, a.z, acc0); acc1 = fmaf(x.w, a.w, acc1);\
        }                                                            \
    }

__global__ void __launch_bounds__(NTHREADS, 1) __cluster_dims__(RB, 1, 1)
nv_main_kernel(
    const float* __restrict__ z0,  const float* __restrict__ h0,
    const float* __restrict__ mean_w, const float* __restrict__ mean_b,
    const float* __restrict__ add_w,
    const float* __restrict__ gsw, const float* __restrict__ gsb_g,
    const float* __restrict__ gcw,
    const float* __restrict__ lw,  const float* __restrict__ lb_g,
    const float* __restrict__ ow,  const float* __restrict__ ob_g,
    const float* __restrict__ wih, const float* __restrict__ whh,
    const float* __restrict__ bih_g, const float* __restrict__ bhh_g,
    const int* __restrict__ src_idx, const int* __restrict__ tgt_idx,
    int T,
    float* __restrict__ zt, float* __restrict__ hf, float* __restrict__ ms)
{
    extern __shared__ char smraw[];
    SmemLayout& sm = *reinterpret_cast<SmemLayout*>(smraw);
    const int tid = threadIdx.x;
    const int g = blockIdx.x / RB;
    const int r = blockIdx.x % RB;
    const int b0 = g * NB_PER;

    // ---- incoming-edge list ----
    for (int e = tid; e < EB; e += NTHREADS) {
        if (tgt_idx[e] == r) {
            int s = src_idx[e];
            int slot = (s < r) ? s : s - 1;
            sm.elist[slot] = e;
            sm.slist[slot] = s;
        }
    }
    if (tid < 2) mbar_init(smem_u32(&sm.mbar[tid]), 88);
    __syncthreads();

    // ---- cache weights ----
    for (int idx = tid; idx < 176*32; idx += NTHREADS) {
        int row = idx >> 5, k = idx & 31;
        int slot = row >> 4, m = row & 15;
        sm.mw2[row*36 + k] = mean_w[((size_t)sm.elist[slot]*MB + m)*LB + k];
    }
    for (int idx = tid; idx < 11*32*16; idx += NTHREADS) {
        int row = idx >> 4, m = idx & 15;           // row = slot*32 + l
        int slot = row >> 5, l = row & 31;
        sm.aw2[row*20 + m] = add_w[((size_t)sm.elist[slot]*LB + l)*MB + m];
    }
    for (int idx = tid; idx < 176; idx += NTHREADS) {
        int slot = idx >> 4, m = idx & 15;
        sm.mb[idx] = mean_b[sm.elist[slot]*MB + m];
    }
    for (int idx = tid; idx < 32*32; idx += NTHREADS) {
        int o = idx >> 5, i = idx & 31;
        sm.gsw2[o*36 + i] = gsw[((size_t)r*LB + o)*LB + i];
        sm.gcw2[o*36 + i] = gcw[((size_t)r*LB + o)*LB + i];
    }
    if (tid < 32) sm.gsb[tid] = gsb_g[r*LB + tid];
    for (int idx = tid; idx < 64*64; idx += NTHREADS) {
        int o = idx >> 6, i = idx & 63;
        sm.lw2[o*68 + i] = lw[((size_t)r*HFB + o)*(2*LB) + i];
    }
    if (tid < 64) sm.lbS[tid] = lb_g[r*HFB + tid];
    for (int idx = tid; idx < 32*64; idx += NTHREADS) {
        int l = idx >> 6, i = idx & 63;
        sm.ow2[l*68 + i] = ow[((size_t)r*LB + l)*HFB + i];
    }
    if (tid < 32) sm.obS[tid] = ob_g[r*LB + tid];
    for (int idx = tid; idx < 96*32; idx += NTHREADS) {
        int j = idx >> 5, i = idx & 31;
        sm.wih2[j*36 + i] = wih[((size_t)r*96 + j)*LB + i];
        sm.whh2[j*36 + i] = whh[((size_t)r*96 + j)*HHB + i];
    }
    if (tid < 96) { sm.bihS[tid] = bih_g[r*96 + tid]; sm.bhhS[tid] = bhh_g[r*96 + tid]; }

    // ---- init state ----
    for (int idx = tid; idx < NB_PER*RB*LB; idx += NTHREADS) {
        int bb = idx / (RB*LB); int rem = idx % (RB*LB);
        int rr = rem >> 5, i = rem & 31;
        sm.zsD[0][bb][rr][i] = z0[((size_t)(b0+bb)*RB + rr)*LB + i];
    }
    for (int idx = tid; idx < NB_PER*HHB; idx += NTHREADS) {
        int bb = idx >> 5, j = idx & 31;
        sm.hgS[bb][j] = h0[((size_t)(b0+bb)*RB + r)*HHB + j];
    }
    __syncthreads();
    cluster_sync_all();

    const int w    = tid >> 5;          // 0..15
    const int lane = tid & 31;

    if (w < 8) {
        // =================== COMPUTE WARP: batch p = w ===================
        const int p = w;
        const int SIG = 2*p, ACK = 2*p + 1;
        const int sub = lane >> 4, m16 = lane & 15;

        const uint32_t smem_base = smem_u32(smraw);
        uint32_t pdelta[11];
        #pragma unroll
        for (int k = 0; k < 11; k++) {
            uint32_t prank = (uint32_t)(k + (k >= r ? 1 : 0));
            pdelta[k] = mapa_rank(smem_base, prank) - smem_base;
        }
        uint32_t laneDelta = 0u;
        #pragma unroll
        for (int k = 0; k < 11; k++)
            if (lane == k) laneDelta = pdelta[k];
        const uint32_t mbar_base = smem_u32(&sm.mbar[0]);

        // per-lane weight row pointers (fixed across steps)
        const float4* wp_gsw = (const float4*)&sm.gsw2[lane*36];
        const float4* wp_gcw = (const float4*)&sm.gcw2[lane*36];
        const float4* wp_lw0a = (const float4*)&sm.lw2[(lane     )*68];
        const float4* wp_lw1a = (const float4*)&sm.lw2[(lane + 32)*68];
        const float4* wp_lw0b = (const float4*)&sm.lw2[(lane     )*68 + 32];
        const float4* wp_lw1b = (const float4*)&sm.lw2[(lane + 32)*68 + 32];
        const float4* wp_ow   = (const float4*)&sm.ow2[lane*68];

        // per-lane mean rows / sources (6 rounds; round 5 invalid for sub=1)
        int mrow_[6], msrc_[6];
        #pragma unroll
        for (int rd = 0; rd < 6; rd++) {
            int slot = 2*rd + sub;
            int slc = (slot < 11) ? slot : 10;
            mrow_[rd] = slc*16 + m16;
            msrc_[rd] = sm.slist[slc];
        }

        int buf3 = 0;
        for (int t = 0; t < T; t++) {
            if (t >= 2) bar_sync64(ACK);     // epi finished step t-2
            const int buf = t & 1;
            const float4* zro = (const float4*)&sm.zsD[buf][p][r][0];

            // ---- S0: own-state dots (overlap peer wait) ----
            float4 za[8];
            #pragma unroll
            for (int q = 0; q < 8; q++) za[q] = zro[q];

            float gspart, lwz0, lwz1;
            {
                float a0 = sm.gsb[lane], a1 = 0.f;
                DOT32(a0, a1, wp_gsw, za);
                gspart = a0 + a1;
            }
            {
                float a0 = sm.lbS[lane], a1 = 0.f;
                DOT32(a0, a1, wp_lw0a, za);
                lwz0 = a0 + a1;
            }
            {
                float a0 = sm.lbS[lane + 32], a1 = 0.f;
                DOT32(a0, a1, wp_lw1a, za);
                lwz1 = a0 + a1;
            }

            // ---- wait peers' z(t-1) ----
            if (t > 0)
                mbar_wait(mbar_base + (uint32_t)(((t - 1) & 1) * 8),
                          (uint32_t)(((t - 1) >> 1) & 1));

            // ---- S1a: ALL 6 mean dots, independent (deep MLP) ----
            float mv[6];
            #pragma unroll
            for (int rd = 0; rd < 6; rd++) {
                const float4* wp = (const float4*)&sm.mw2[mrow_[rd]*36];
                const float4* ap = (const float4*)&sm.zsD[buf][p][msrc_[rd]][0];
                float a0 = sm.mb[mrow_[rd]], a1 = 0.f;
                DOT32(a0, a1, wp, ap);
                mv[rd] = a0 + a1;
            }
            {
                float* mrowp = &sm.meanF[buf3][p][0];
                #pragma unroll
                for (int rd = 0; rd < 6; rd++)
                    if (2*rd + sub < 11) mrowp[mrow_[rd]] = mv[rd];
            }
            __syncwarp();

            // ---- S1b: ALL 11 projection blocks, 8 accumulators ----
            {
                const float4* mp = (const float4*)&sm.meanF[buf3][p][0];
                float a0=0.f,a1=0.f,a2=0.f,a3=0.f,a4=0.f,a5=0.f,a6=0.f,a7=0.f;
                #pragma unroll
                for (int sl = 0; sl < 11; sl++) {
                    const float4* wpj = (const float4*)&sm.aw2[(sl*32 + lane)*20];
                    const float4* apj = mp + sl*4;
                    float4 x0 = wpj[0], v0 = apj[0];
                    float4 x1 = wpj[1], v1 = apj[1];
                    float4 x2 = wpj[2], v2 = apj[2];
                    float4 x3 = wpj[3], v3 = apj[3];
                    a0 = fmaf(x0.x, v0.x, a0); a1 = fmaf(x0.y, v0.y, a1);
                    a2 = fmaf(x0.z, v0.z, a2); a3 = fmaf(x0.w, v0.w, a3);
                    a4 = fmaf(x1.x, v1.x, a4); a5 = fmaf(x1.y, v1.y, a5);
                    a6 = fmaf(x1.z, v1.z, a6); a7 = fmaf(x1.w, v1.w, a7);
                    a0 = fmaf(x2.x, v2.x, a0); a1 = fmaf(x2.y, v2.y, a1);
                    a2 = fmaf(x2.z, v2.z, a2); a3 = fmaf(x2.w, v2.w, a3);
                    a4 = fmaf(x3.x, v3.x, a4); a5 = fmaf(x3.y, v3.y, a5);
                    a6 = fmaf(x3.z, v3.z, a6); a7 = fmaf(x3.w, v3.w, a7);
                }
                sm.incD[buf3][p][lane] = ((a0 + a1) + (a2 + a3)) + ((a4 + a5) + (a6 + a7));
            }
            __syncwarp();

            // ---- S2: gate + hidden inc-half (3 independent dots) ----
            float4 ia[8];
            {
                const float4* ip = (const float4*)&sm.incD[buf3][p][0];
                #pragma unroll
                for (int q = 0; q < 8; q++) ia[q] = ip[q];
            }
            float gate;
            {
                float a0 = gspart, a1 = 0.f;
                DOT32(a0, a1, wp_gcw, ia);
                gate = fsig(a0 + a1);
            }
            {
                float a0 = lwz0, a1 = 0.f;
                DOT32(a0, a1, wp_lw0b, ia);
                const float v = a0 + a1;
                sm.hbufT[p][lane] = v * fsig(v);
            }
            {
                float a0 = lwz1, a1 = 0.f;
                DOT32(a0, a1, wp_lw1b, ia);
                const float v = a0 + a1;
                sm.hbufT[p][lane + 32] = v * fsig(v);
            }
            __syncwarp();

            // ---- S3: out layer + z update + publish ----
            {
                const float4* ap = (const float4*)&sm.hbufT[p][0];
                float a0 = sm.obS[lane], a1 = 0.f, a2 = 0.f, a3 = 0.f;
                #pragma unroll
                for (int q = 0; q < 16; q++) {
                    float4 x = wp_ow[q], a = ap[q];
                    a0 = fmaf(x.x, a.x, a0); a1 = fmaf(x.y, a.y, a1);
                    a2 = fmaf(x.z, a.z, a2); a3 = fmaf(x.w, a.w, a3);
                }
                const float target = tanhf((a0 + a1) + (a2 + a3));
                const float zold = sm.zsD[buf][p][r][lane];
                const float znew = fmaf(0.1f * gate, target - zold, zold);

                const int nxt = buf ^ 1;
                sm.zsD[nxt][p][r][lane] = znew;
                sm.zpub[buf3][p][lane]  = znew;
                const uint32_t zaddr = smem_base +
                    (uint32_t)((const char*)&sm.zsD[nxt][p][r][lane] - (const char*)&sm);
                #pragma unroll
                for (int k = 0; k < 11; k++)
                    st_remote_f32(zaddr + pdelta[k], znew);
                __syncwarp();
                if (lane < 11)
                    mbar_arrive_remote(mbar_base + (uint32_t)((t & 1) * 8) + laneDelta);
            }
            bar_arrive64(SIG);               // step-t data ready for epilogue

            buf3 = (buf3 == 2) ? 0 : buf3 + 1;
        }
    } else {
        // =================== EPILOGUE WARP: batch p = w-8 ===================
        const int p = w - 8;
        const int SIG = 2*p, ACK = 2*p + 1;
        float hnew = 0.0f;

        const float4* w0h = (const float4*)&sm.whh2[(lane   )*36];
        const float4* w1h = (const float4*)&sm.whh2[(lane+32)*36];
        const float4* w2h = (const float4*)&sm.whh2[(lane+64)*36];
        const float4* w0i = (const float4*)&sm.wih2[(lane   )*36];
        const float4* w1i = (const float4*)&sm.wih2[(lane+32)*36];
        const float4* w2i = (const float4*)&sm.wih2[(lane+64)*36];

        int buf3 = 0;
        for (int t = 0; t < T; t++) {
            // whh dots on own h (before SIG — h is epi-local)
            float gh0, gh1, gh2;
            {
                const float4* hp = (const float4*)&sm.hgS[p][0];
                float4 ha[8];
                #pragma unroll
                for (int q = 0; q < 8; q++) ha[q] = hp[q];
                float a0 = sm.bhhS[lane],     a1 = 0.f;
                float b0a = sm.bhhS[lane+32], b1a = 0.f;
                float c0 = sm.bhhS[lane+64],  c1 = 0.f;
                #pragma unroll
                for (int q = 0; q < 8; q++) {
                    float4 a = ha[q];
                    float4 x0 = w0h[q], x1 = w1h[q], x2 = w2h[q];
                    a0  = fmaf(x0.x, a.x, a0 ); a1  = fmaf(x0.y, a.y, a1 );
                    a0  = fmaf(x0.z, a.z, a0 ); a1  = fmaf(x0.w, a.w, a1 );
                    b0a = fmaf(x1.x, a.x, b0a); b1a = fmaf(x1.y, a.y, b1a);
                    b0a = fmaf(x1.z, a.z, b0a); b1a = fmaf(x1.w, a.w, b1a);
                    c0  = fmaf(x2.x, a.x, c0 ); c1  = fmaf(x2.y, a.y, c1 );
                    c0  = fmaf(x2.z, a.z, c0 ); c1  = fmaf(x2.w, a.w, c1 );
                }
                gh0 = a0 + a1; gh1 = b0a + b1a; gh2 = c0 + c1;
            }

            bar_sync64(SIG);                 // compute published step t

            // wih dots + GRU
            {
                const float4* ip = (const float4*)&sm.incD[buf3][p][0];
                float4 ia[8];
                #pragma unroll
                for (int q = 0; q < 8; q++) ia[q] = ip[q];
                float g0a = sm.bihS[lane],    g0b = 0.f;
                float g1a = sm.bihS[lane+32], g1b = 0.f;
                float g2a = sm.bihS[lane+64], g2b = 0.f;
                #pragma unroll
                for (int q = 0; q < 8; q++) {
                    float4 a = ia[q];
                    float4 x0 = w0i[q], x1 = w1i[q], x2 = w2i[q];
                    g0a = fmaf(x0.x, a.x, g0a); g0b = fmaf(x0.y, a.y, g0b);
                    g0a = fmaf(x0.z, a.z, g0a); g0b = fmaf(x0.w, a.w, g0b);
                    g1a = fmaf(x1.x, a.x, g1a); g1b = fmaf(x1.y, a.y, g1b);
                    g1a = fmaf(x1.z, a.z, g1a); g1b = fmaf(x1.w, a.w, g1b);
                    g2a = fmaf(x2.x, a.x, g2a); g2b = fmaf(x2.y, a.y, g2b);
                    g2a = fmaf(x2.z, a.z, g2a); g2b = fmaf(x2.w, a.w, g2b);
                }
                const float gr = fsig((g0a + g0b) + gh0);
                const float gz = fsig((g1a + g1b) + gh1);
                const float nn = tanhf(fmaf(gr, gh2, g2a + g2b));
                const float hold = sm.hgS[p][lane];
                hnew = (1.0f - gz)*nn + gz*hold;
                sm.hgS[p][lane] = hnew;
            }
            __syncwarp();

            // global stores (zt, ms)
            zt[(((size_t)(b0 + p)*T + t)*RB + r)*LB + lane] = sm.zpub[buf3][p][lane];
            {
                float* msrow = ms + ((size_t)(b0 + p)*T + t)*(EB*MB);
                #pragma unroll
                for (int j = 0; j < 6; j++) {
                    const int idx = j*32 + lane;
                    if (idx < 176)
                        msrow[sm.elist[idx >> 4]*MB + (idx & 15)] = sm.meanF[buf3][p][idx];
                }
            }

            if (t < T - 2) bar_arrive64(ACK);
            buf3 = (buf3 == 2) ? 0 : buf3 + 1;
        }

        hf[((size_t)(b0 + p)*RB + r)*HHB + lane] = hnew;
    }

    cluster_sync_all();   // peers may still be writing our smem
}

extern "C" void kernel_launch(void* const* d_in, const int* in_sizes, int n_in,
                              void* d_out, int out_size) {
    const float* z0     = (const float*)d_in[0];
    const float* h0     = (const float*)d_in[1];
    const float* mean_w = (const float*)d_in[2];
    const float* mean_b = (const float*)d_in[3];
    const float* add_w  = (const float*)d_in[4];
    const float* gsw    = (const float*)d_in[5];
    const float* gsb    = (const float*)d_in[6];
    const float* gcw    = (const float*)d_in[7];
    const float* lw     = (const float*)d_in[8];
    const float* lb     = (const float*)d_in[9];
    const float* ow     = (const float*)d_in[10];
    const float* ob     = (const float*)d_in[11];
    const float* wih    = (const float*)d_in[12];
    const float* whh    = (const float*)d_in[13];
    const float* bih    = (const float*)d_in[14];
    const float* bhh    = (const float*)d_in[15];
    const int* src_idx  = (const int*)d_in[16];
    const int* tgt_idx  = (const int*)d_in[17];
    // out_size = B*T*R*L + B*R*Hh + B*T*E*M
    const int per_t = BTOT*RB*LB + BTOT*EB*MB;
    const int T = (out_size - BTOT*RB*HHB) / per_t;

    float* out = (float*)d_out;
    float* zt = out;
    float* hf = zt + (size_t)BTOT * T * RB * LB;
    float* ms = hf + (size_t)BTOT * RB * HHB;

    cudaFuncSetAttribute(nv_main_kernel,
                         cudaFuncAttributeMaxDynamicSharedMemorySize,
                         (int)sizeof(SmemLayout));
    cudaFuncSetAttribute(nv_main_kernel,
                         cudaFuncAttributeNonPortableClusterSizeAllowed, 1);

    nv_main_kernel<<<NBLOCKS, NTHREADS, sizeof(SmemLayout)>>>(
        z0, h0, mean_w, mean_b, add_w, gsw, gsb, gcw, lw, lb, ow, ob,
        wih, whh, bih, bhh, src_idx, tgt_idx, T, zt, hf, ms);
}